// round 3
// baseline (speedup 1.0000x reference)
#include <cuda_runtime.h>
#include <cuda_bf16.h>

#define U 64
#define M 8192
#define D 64
#define CHUNK 512
#define NCHUNK (M / CHUNK)   // 16
#define BLOCK 256
#define NWARP (BLOCK / 32)   // 8

#define NEG_INF_F __int_as_float(0xff800000)

// Device scratch (no allocations allowed)
__device__ float g_cmax[U * NCHUNK];
__device__ float g_csum[U * NCHUNK];
__device__ float g_partial[U * NCHUNK * D];

// ---------------------------------------------------------------------------
// Kernel 1: scores + per-chunk softmax stats.
// grid (NCHUNK, U), block 256. One warp computes one slot's dot product
// (float2 per lane = 256B coalesced per slot). Scores go into the weights
// region of d_out (scratch; overwritten with weights in kernel 2).
// ---------------------------------------------------------------------------
__global__ void __launch_bounds__(BLOCK)
k_scores(const float* __restrict__ q,      // [U, D]
         const float* __restrict__ keys,   // [U, M, D]
         const int*   __restrict__ mask,   // [U, M] (0/1; int32 or float32 bits)
         const float* __restrict__ tmpr,   // [U, 1]
         float* __restrict__ scores)       // [U, M]
{
    __shared__ float s_s[CHUNK];
    __shared__ float s_red[NWARP];

    const int u = blockIdx.y, c = blockIdx.x;
    const int tid = threadIdx.x, lane = tid & 31, warp = tid >> 5;
    const int m0 = c * CHUNK;

    const float2 q2 = ((const float2*)(q + u * D))[lane];
    const float t = tmpr[u];

    #pragma unroll 4
    for (int i = warp; i < CHUNK; i += NWARP) {
        const int m = m0 + i;
        const float2 k2 = ((const float2*)(keys + ((size_t)(u * M + m)) * D))[lane];
        float p = k2.x * q2.x + k2.y * q2.y;
        #pragma unroll
        for (int o = 16; o > 0; o >>= 1) p += __shfl_xor_sync(0xffffffffu, p, o);
        if (lane == 0) {
            float s = (mask[u * M + m] != 0) ? -1e9f : p;
            s = s / t;
            s_s[i] = s;
            scores[(size_t)u * M + m] = s;
        }
    }
    __syncthreads();

    // block max over the chunk
    float lm = NEG_INF_F;
    #pragma unroll
    for (int i = tid; i < CHUNK; i += BLOCK) lm = fmaxf(lm, s_s[i]);
    #pragma unroll
    for (int o = 16; o > 0; o >>= 1) lm = fmaxf(lm, __shfl_xor_sync(0xffffffffu, lm, o));
    if (lane == 0) s_red[warp] = lm;
    __syncthreads();
    float cmax;
    {
        float mx = s_red[0];
        #pragma unroll
        for (int w = 1; w < NWARP; w++) mx = fmaxf(mx, s_red[w]);
        cmax = mx;     // every thread reads all of s_red
    }
    __syncthreads();   // protect s_red reuse below

    // block sum of exp(s - cmax)
    float ls = 0.0f;
    #pragma unroll
    for (int i = tid; i < CHUNK; i += BLOCK) ls += __expf(s_s[i] - cmax);
    #pragma unroll
    for (int o = 16; o > 0; o >>= 1) ls += __shfl_xor_sync(0xffffffffu, ls, o);
    if (lane == 0) s_red[warp] = ls;
    __syncthreads();
    if (tid == 0) {
        float sm = 0.0f;
        #pragma unroll
        for (int w = 0; w < NWARP; w++) sm += s_red[w];
        g_cmax[u * NCHUNK + c] = cmax;
        g_csum[u * NCHUNK + c] = sm;
    }
}

// ---------------------------------------------------------------------------
// Kernel 2: global softmax recombine, weights in place, weighted memory sum
// into deterministic per-chunk partials + FUSED memories copy (memories is
// read exactly once for both the einsum and the output copy).
// grid (NCHUNK, U), block 256.
// ---------------------------------------------------------------------------
__global__ void __launch_bounds__(BLOCK)
k_out(const float* __restrict__ mem,       // [U, M, D]
      float* __restrict__ weights,         // [U, M] (holds scores on entry)
      float* __restrict__ memout)          // [U, M, D]
{
    const int u = blockIdx.y, c = blockIdx.x;
    const int tid = threadIdx.x, lane = tid & 31, warp = tid >> 5;
    const int m0 = c * CHUNK;

    // Global softmax stats from the 16 chunk stats (flash-style recombine)
    float gmax = NEG_INF_F;
    #pragma unroll
    for (int j = 0; j < NCHUNK; j++) gmax = fmaxf(gmax, g_cmax[u * NCHUNK + j]);
    float gsum = 0.0f;
    #pragma unroll
    for (int j = 0; j < NCHUNK; j++)
        gsum += g_csum[u * NCHUNK + j] * __expf(g_cmax[u * NCHUNK + j] - gmax);
    const float inv = 1.0f / gsum;

    float2 acc = make_float2(0.0f, 0.0f);
    #pragma unroll 4
    for (int i = warp; i < CHUNK; i += NWARP) {
        const int m = m0 + i;
        const float s = weights[(size_t)u * M + m];          // score, broadcast load
        const float w = __expf(s - gmax) * inv;
        const size_t base = ((size_t)(u * M + m)) * D;
        const float2 mv = ((const float2*)(mem + base))[lane];
        acc.x = fmaf(w, mv.x, acc.x);
        acc.y = fmaf(w, mv.y, acc.y);
        ((float2*)(memout + base))[lane] = mv;               // fused memories copy
        if (lane == 0) weights[(size_t)u * M + m] = w;       // score -> weight
    }

    __shared__ float2 s_acc[NWARP][32];
    s_acc[warp][lane] = acc;
    __syncthreads();
    if (warp == 0) {
        float2 tsum = s_acc[0][lane];
        #pragma unroll
        for (int w = 1; w < NWARP; w++) {
            tsum.x += s_acc[w][lane].x;
            tsum.y += s_acc[w][lane].y;
        }
        const int pbase = (u * NCHUNK + c) * D;
        g_partial[pbase + 2 * lane]     = tsum.x;
        g_partial[pbase + 2 * lane + 1] = tsum.y;
    }
}

// ---------------------------------------------------------------------------
// Kernel 3: reduce chunk partials -> outputs. grid U, block D. Deterministic.
// ---------------------------------------------------------------------------
__global__ void k_red(float* __restrict__ outp)             // [U, D]
{
    const int u = blockIdx.x, d = threadIdx.x;
    float s = 0.0f;
    #pragma unroll
    for (int c = 0; c < NCHUNK; c++) s += g_partial[(u * NCHUNK + c) * D + d];
    outp[u * D + d] = s;
}

extern "C" void kernel_launch(void* const* d_in, const int* in_sizes, int n_in,
                              void* d_out, int out_size)
{
    const float* attention  = (const float*)d_in[0];  // [U, D]
    const float* attentions = (const float*)d_in[1];  // [U, M, D]
    const float* memories   = (const float*)d_in[2];  // [U, M, D]
    const float* tmpr       = (const float*)d_in[3];  // [U, 1]
    const int*   mask       = (const int*)  d_in[4];  // [U, M]

    float* out          = (float*)d_out;
    float* out_outputs  = out;                        // [U, D]
    float* out_weights  = out + U * D;                // [U, M]
    float* out_memories = out + U * D + U * M;        // [U, M, D]

    dim3 grid(NCHUNK, U);
    k_scores<<<grid, BLOCK>>>(attention, attentions, mask, tmpr, out_weights);
    k_out<<<grid, BLOCK>>>(memories, out_weights, out_memories);
    k_red<<<U, D>>>(out_outputs);
}

// round 4
// speedup vs baseline: 3.4516x; 3.4516x over previous
#include <cuda_runtime.h>
#include <cuda_bf16.h>

#define U 64
#define M 8192
#define D 64
#define CHUNK 512
#define NCHUNK (M / CHUNK)   // 16
#define BLOCK 256
#define NWARP (BLOCK / 32)   // 8

#define NEG_INF_F __int_as_float(0xff800000)

// Device scratch (no allocations allowed)
__device__ float  g_cmax[U * NCHUNK];
__device__ float  g_csum[U * NCHUNK];
__device__ float4 g_partial4[U * NCHUNK * (D / 4)];

// ---------------------------------------------------------------------------
// Kernel 1: scores + per-chunk softmax stats.
// grid (NCHUNK, U), block 256.
// Phase 1: dot products. 16 lanes per slot (float4/lane), 2 slots per warp
//          iteration -> warp reads 512B contiguous, 4 shfls per 2 slots.
// Phase 2: coalesced mask+temperature+score write + block max/sum stats.
// ---------------------------------------------------------------------------
__global__ void __launch_bounds__(BLOCK)
k_scores(const float* __restrict__ q,      // [U, D]
         const float* __restrict__ keys,   // [U, M, D]
         const int*   __restrict__ mask,   // [U, M] (0/1 int32)
         const float* __restrict__ tmpr,   // [U, 1]
         float* __restrict__ scores)       // [U, M]
{
    __shared__ float s_s[CHUNK];
    __shared__ float s_red[NWARP];

    const int u = blockIdx.y, c = blockIdx.x;
    const int tid = threadIdx.x, lane = tid & 31, warp = tid >> 5;
    const int sub = lane & 15, half = lane >> 4;
    const int m0 = c * CHUNK;

    const float4 q4 = ((const float4*)(q + u * D))[sub];

    // ---- Phase 1: raw dots into smem ----
    const int base_slot = warp * (CHUNK / NWARP);            // 64 slots per warp
    #pragma unroll 4
    for (int i = 0; i < (CHUNK / NWARP) / 2; i++) {          // 32 iterations
        const int j = base_slot + 2 * i + half;              // slot within chunk
        const size_t row = ((size_t)(u * M + m0 + j)) * D;
        const float4 k4 = ((const float4*)(keys + row))[sub];
        float p = k4.x * q4.x + k4.y * q4.y + k4.z * q4.z + k4.w * q4.w;
        #pragma unroll
        for (int o = 1; o < 16; o <<= 1) p += __shfl_xor_sync(0xffffffffu, p, o);
        if (sub == 0) s_s[j] = p;
    }
    __syncthreads();

    // ---- Phase 2: mask + temperature, coalesced global write, stats ----
    const float t = tmpr[u];
    const int j2 = tid * 2;
    const float2 sv = *(const float2*)&s_s[j2];
    const int2  mk = ((const int2*)(mask + u * M + m0))[tid];
    float s0 = (mk.x != 0) ? -1e9f : sv.x;
    float s1 = (mk.y != 0) ? -1e9f : sv.y;
    s0 = s0 / t;
    s1 = s1 / t;
    ((float2*)(scores + (size_t)u * M + m0))[tid] = make_float2(s0, s1);

    // block max
    float lm = fmaxf(s0, s1);
    #pragma unroll
    for (int o = 16; o > 0; o >>= 1) lm = fmaxf(lm, __shfl_xor_sync(0xffffffffu, lm, o));
    if (lane == 0) s_red[warp] = lm;
    __syncthreads();
    float cmax = s_red[0];
    #pragma unroll
    for (int w = 1; w < NWARP; w++) cmax = fmaxf(cmax, s_red[w]);
    __syncthreads();   // protect s_red reuse

    // block sum of exp(s - cmax)
    float ls = __expf(s0 - cmax) + __expf(s1 - cmax);
    #pragma unroll
    for (int o = 16; o > 0; o >>= 1) ls += __shfl_xor_sync(0xffffffffu, ls, o);
    if (lane == 0) s_red[warp] = ls;
    __syncthreads();
    if (tid == 0) {
        float sm = 0.0f;
        #pragma unroll
        for (int w = 0; w < NWARP; w++) sm += s_red[w];
        g_cmax[u * NCHUNK + c] = cmax;
        g_csum[u * NCHUNK + c] = sm;
    }
}

// ---------------------------------------------------------------------------
// Kernel 2: recombine -> weights (coalesced, via smem), weighted memory sum
// into deterministic per-chunk partials + fused memories copy (float4 streams).
// grid (NCHUNK, U), block 256.
// ---------------------------------------------------------------------------
__global__ void __launch_bounds__(BLOCK)
k_out(const float* __restrict__ mem,       // [U, M, D]
      float* __restrict__ weights,         // [U, M] (scores on entry)
      float* __restrict__ memout)          // [U, M, D]
{
    __shared__ float  s_w[CHUNK];
    __shared__ float4 s_acc[NWARP][32];

    const int u = blockIdx.y, c = blockIdx.x;
    const int tid = threadIdx.x, lane = tid & 31, warp = tid >> 5;
    const int sub = lane & 15, half = lane >> 4;
    const int m0 = c * CHUNK;

    // ---- global softmax stats (flash recombine, broadcast loads) ----
    float gmax = NEG_INF_F;
    #pragma unroll
    for (int j = 0; j < NCHUNK; j++) gmax = fmaxf(gmax, g_cmax[u * NCHUNK + j]);
    float gsum = 0.0f;
    #pragma unroll
    for (int j = 0; j < NCHUNK; j++)
        gsum += g_csum[u * NCHUNK + j] * __expf(g_cmax[u * NCHUNK + j] - gmax);
    const float inv = 1.0f / gsum;

    // ---- Phase 1: all chunk weights, coalesced (read scores, write weights) ----
    const int j2 = tid * 2;
    const float2 sv = ((const float2*)(weights + (size_t)u * M + m0))[tid];
    const float w0 = __expf(sv.x - gmax) * inv;
    const float w1 = __expf(sv.y - gmax) * inv;
    s_w[j2]     = w0;
    s_w[j2 + 1] = w1;
    ((float2*)(weights + (size_t)u * M + m0))[tid] = make_float2(w0, w1);
    __syncthreads();

    // ---- Phase 2: stream memories once: weighted sum + fused copy ----
    float4 acc = make_float4(0.0f, 0.0f, 0.0f, 0.0f);
    const int base_slot = warp * (CHUNK / NWARP);
    #pragma unroll 4
    for (int i = 0; i < (CHUNK / NWARP) / 2; i++) {
        const int j = base_slot + 2 * i + half;
        const size_t row = ((size_t)(u * M + m0 + j)) * D;
        const float4 mv = ((const float4*)(mem + row))[sub];
        const float w = s_w[j];                               // smem broadcast
        acc.x = fmaf(w, mv.x, acc.x);
        acc.y = fmaf(w, mv.y, acc.y);
        acc.z = fmaf(w, mv.z, acc.z);
        acc.w = fmaf(w, mv.w, acc.w);
        ((float4*)(memout + row))[sub] = mv;                  // fused copy
    }
    s_acc[warp][lane] = acc;
    __syncthreads();

    // ---- Phase 3: reduce 16 partial vectors (8 warps x 2 halves) ----
    if (tid < 16) {
        float4 tsum = make_float4(0.0f, 0.0f, 0.0f, 0.0f);
        #pragma unroll
        for (int w = 0; w < NWARP; w++) {
            #pragma unroll
            for (int h = 0; h < 2; h++) {
                const float4 v = s_acc[w][h * 16 + tid];
                tsum.x += v.x; tsum.y += v.y; tsum.z += v.z; tsum.w += v.w;
            }
        }
        g_partial4[(u * NCHUNK + c) * (D / 4) + tid] = tsum;
    }
}

// ---------------------------------------------------------------------------
// Kernel 3: reduce chunk partials -> outputs. grid U, block D. Deterministic.
// ---------------------------------------------------------------------------
__global__ void k_red(float* __restrict__ outp)               // [U, D]
{
    const int u = blockIdx.x, d = threadIdx.x;
    const float* gp = (const float*)g_partial4;
    float s = 0.0f;
    #pragma unroll
    for (int c = 0; c < NCHUNK; c++) s += gp[(u * NCHUNK + c) * D + d];
    outp[u * D + d] = s;
}

extern "C" void kernel_launch(void* const* d_in, const int* in_sizes, int n_in,
                              void* d_out, int out_size)
{
    const float* attention  = (const float*)d_in[0];  // [U, D]
    const float* attentions = (const float*)d_in[1];  // [U, M, D]
    const float* memories   = (const float*)d_in[2];  // [U, M, D]
    const float* tmpr       = (const float*)d_in[3];  // [U, 1]
    const int*   mask       = (const int*)  d_in[4];  // [U, M]

    float* out          = (float*)d_out;
    float* out_outputs  = out;                        // [U, D]
    float* out_weights  = out + U * D;                // [U, M]
    float* out_memories = out + U * D + U * M;        // [U, M, D]

    dim3 grid(NCHUNK, U);
    k_scores<<<grid, BLOCK>>>(attention, attentions, mask, tmpr, out_weights);
    k_out<<<grid, BLOCK>>>(memories, out_weights, out_memories);
    k_red<<<U, D>>>(out_outputs);
}